// round 3
// baseline (speedup 1.0000x reference)
#include <cuda_runtime.h>
#include <cuda_bf16.h>
#include <math.h>

// Problem dims
#define Bz 32
#define Nz 1024
#define Cz 1024
#define Lz 16
#define C2z 512
#define CH 512   // C-half tile

// ---------------- scratch (static device memory, no allocs) ----------------
__device__ float g_E[Bz * Nz * Lz];      // exp(proj), unnormalized
__device__ float g_S[Bz * Lz];           // softmax column sums
__device__ float g_T[Bz * Lz * Cz];      // tokens
__device__ float g_k[Bz * Lz * C2z];
__device__ float g_q[Bz * Lz * C2z];
__device__ float g_Td[Bz * Lz * Cz];     // T_dash
__device__ float g_H[Bz * Lz * Cz];      // relu hidden
__device__ float g_Tk[Bz * Lz * Cz];     // T_out @ k_W + k_b
__device__ float g_M[Bz * Lz * Cz];      // M[b][l][c] = sum_c' q_W[c][c']*Tk[b][l][c']
__device__ float g_s0[Bz * Lz];          // q_b . Tk[b][l]

// ---------------- K1: E = exp(X @ tok_W + tok_b) ----------------
// 32 rows/block, warp handles 4 rows. tok_W kept in smem in two 512-col halves (32KB).
__global__ __launch_bounds__(256) void k1_proj_exp(
    const float* __restrict__ X, const float* __restrict__ tokW,
    const float* __restrict__ tokb)
{
    __shared__ float Ws[16][CH];  // 32KB
    int tid = threadIdx.x;
    int warp = tid >> 5, lane = tid & 31;
    int row0 = blockIdx.x * 32 + warp * 4;  // row in [0, B*N)

    float acc[4][16];
    #pragma unroll
    for (int i = 0; i < 4; i++)
        #pragma unroll
        for (int l = 0; l < 16; l++) acc[i][l] = 0.f;

    for (int ch = 0; ch < 2; ch++) {
        __syncthreads();
        for (int idx = tid; idx < CH * 16; idx += 256) {
            int c = idx >> 4, l = idx & 15;
            Ws[l][c] = tokW[(ch * CH + c) * Lz + l];
        }
        __syncthreads();

        const float4* x0 = (const float4*)(X + (size_t)(row0 + 0) * Cz + ch * CH);
        const float4* x1 = (const float4*)(X + (size_t)(row0 + 1) * Cz + ch * CH);
        const float4* x2 = (const float4*)(X + (size_t)(row0 + 2) * Cz + ch * CH);
        const float4* x3 = (const float4*)(X + (size_t)(row0 + 3) * Cz + ch * CH);
        const float4* Ws4 = (const float4*)Ws;

        #pragma unroll
        for (int jj = 0; jj < 4; jj++) {
            int c4 = jj * 32 + lane;
            float4 xv0 = x0[c4], xv1 = x1[c4], xv2 = x2[c4], xv3 = x3[c4];
            #pragma unroll
            for (int l = 0; l < 16; l++) {
                float4 w = Ws4[l * (CH / 4) + c4];
                acc[0][l] += xv0.x * w.x + xv0.y * w.y + xv0.z * w.z + xv0.w * w.w;
                acc[1][l] += xv1.x * w.x + xv1.y * w.y + xv1.z * w.z + xv1.w * w.w;
                acc[2][l] += xv2.x * w.x + xv2.y * w.y + xv2.z * w.z + xv2.w * w.w;
                acc[3][l] += xv3.x * w.x + xv3.y * w.y + xv3.z * w.z + xv3.w * w.w;
            }
        }
    }
    float bv = (lane < 16) ? tokb[lane] : 0.f;
    #pragma unroll
    for (int i = 0; i < 4; i++) {
        float myv = 0.f;
        #pragma unroll
        for (int l = 0; l < 16; l++) {
            float v = acc[i][l];
            v += __shfl_xor_sync(0xffffffffu, v, 16);
            v += __shfl_xor_sync(0xffffffffu, v, 8);
            v += __shfl_xor_sync(0xffffffffu, v, 4);
            v += __shfl_xor_sync(0xffffffffu, v, 2);
            v += __shfl_xor_sync(0xffffffffu, v, 1);
            if (lane == l) myv = v;
        }
        if (lane < 16) g_E[(row0 + i) * Lz + lane] = expf(myv + bv);
    }
}

// ---------------- K2: S[b][l] = sum_n E[b][n][l] ----------------
__global__ __launch_bounds__(512) void k2_colsum()
{
    int b = blockIdx.x;
    int tid = threadIdx.x;
    int l = tid & 15, ng = tid >> 4;  // 32 groups
    float s = 0.f;
    for (int n = ng; n < Nz; n += 32) s += g_E[(b * Nz + n) * Lz + l];
    __shared__ float red[32][16];
    red[ng][l] = s;
    __syncthreads();
    if (tid < 16) {
        float t = 0.f;
        #pragma unroll
        for (int g = 0; g < 32; g++) t += red[g][tid];
        g_S[b * Lz + tid] = t;
    }
}

// ---------------- K3: T[b][l][c] = (1/S) sum_n E[b][n][l] * X[b][n][c] ----------------
__global__ __launch_bounds__(256) void k3_aggregate(const float* __restrict__ X)
{
    int b = blockIdx.y;
    int c0 = blockIdx.x * 128;
    int tid = threadIdx.x;
    int tx = tid & 127, ty = tid >> 7;  // ty in {0,1}

    __shared__ float Es[64][16];
    __shared__ float red[16][128];

    float acc[16];
    #pragma unroll
    for (int l = 0; l < 16; l++) acc[l] = 0.f;

    for (int n0 = 0; n0 < Nz; n0 += 64) {
        __syncthreads();
        for (int idx = tid; idx < 64 * 16; idx += 256)
            Es[idx >> 4][idx & 15] = g_E[(b * Nz + n0 + (idx >> 4)) * Lz + (idx & 15)];
        __syncthreads();
        #pragma unroll 4
        for (int jj = 0; jj < 32; jj++) {
            int nl = jj * 2 + ty;
            float x = X[(size_t)(b * Nz + n0 + nl) * Cz + c0 + tx];
            #pragma unroll
            for (int l = 0; l < 16; l++) acc[l] += Es[nl][l] * x;
        }
    }
    __syncthreads();
    if (ty == 1) {
        #pragma unroll
        for (int l = 0; l < 16; l++) red[l][tx] = acc[l];
    }
    __syncthreads();
    if (ty == 0) {
        #pragma unroll
        for (int l = 0; l < 16; l++) {
            float v = acc[l] + red[l][tx];
            g_T[(b * Lz + l) * Cz + c0 + tx] = v / g_S[b * Lz + l];
        }
    }
}

// ---------------- generic tiled GEMM: out = act(A @ W + bias [+ residual]) ----------------
// Compile-time selectors bind device scratch arrays (no host symbol lookups).
// ASEL: 0=g_T 1=g_Td 2=g_H 3=external   OSEL: 0=g_k 1=g_q 2=g_H 4=g_Tk 3=external
// RSEL: 0=none 1=g_Td
template<int ASEL, int OSEL, int RSEL, int RELU>
__global__ __launch_bounds__(256) void gemm_bias(
    const float* __restrict__ Aext, const float* __restrict__ W,
    const float* __restrict__ bias, float* __restrict__ Oext,
    int K, int Nout)
{
    const float* A = (ASEL == 0) ? g_T : (ASEL == 1) ? g_Td : (ASEL == 2) ? g_H : Aext;
    float* out = (OSEL == 0) ? g_k : (OSEL == 1) ? g_q : (OSEL == 2) ? g_H
               : (OSEL == 4) ? g_Tk : Oext;

    __shared__ float As[16][64];
    __shared__ float Ws[16][64];
    int tid = threadIdx.x;
    int r0 = blockIdx.y * 64;
    int c0 = blockIdx.x * 64;
    int tm = tid >> 4, tn = tid & 15;
    int lr = tid >> 2, lk = (tid & 3) << 2;
    int wk = tid >> 4, wn = (tid & 15) << 2;

    float acc[4][4];
    #pragma unroll
    for (int i = 0; i < 4; i++)
        #pragma unroll
        for (int j = 0; j < 4; j++) acc[i][j] = 0.f;

    for (int k0 = 0; k0 < K; k0 += 16) {
        float4 a = *(const float4*)(A + (size_t)(r0 + lr) * K + k0 + lk);
        As[lk + 0][lr] = a.x; As[lk + 1][lr] = a.y;
        As[lk + 2][lr] = a.z; As[lk + 3][lr] = a.w;
        *(float4*)&Ws[wk][wn] = *(const float4*)(W + (size_t)(k0 + wk) * Nout + c0 + wn);
        __syncthreads();
        #pragma unroll
        for (int kk = 0; kk < 16; kk++) {
            float4 av = *(float4*)&As[kk][tm * 4];
            float4 wv = *(float4*)&Ws[kk][tn * 4];
            float ar[4] = {av.x, av.y, av.z, av.w};
            float wr[4] = {wv.x, wv.y, wv.z, wv.w};
            #pragma unroll
            for (int i = 0; i < 4; i++)
                #pragma unroll
                for (int j = 0; j < 4; j++) acc[i][j] += ar[i] * wr[j];
        }
        __syncthreads();
    }
    int cb = c0 + tn * 4;
    float b0 = bias[cb + 0], b1 = bias[cb + 1], b2 = bias[cb + 2], b3 = bias[cb + 3];
    #pragma unroll
    for (int i = 0; i < 4; i++) {
        int r = r0 + tm * 4 + i;
        float o0 = acc[i][0] + b0, o1 = acc[i][1] + b1;
        float o2 = acc[i][2] + b2, o3 = acc[i][3] + b3;
        if (RSEL == 1) {
            float4 rv = *(const float4*)(g_Td + (size_t)r * Nout + cb);
            o0 += rv.x; o1 += rv.y; o2 += rv.z; o3 += rv.w;
        }
        if (RELU) {
            o0 = fmaxf(o0, 0.f); o1 = fmaxf(o1, 0.f);
            o2 = fmaxf(o2, 0.f); o3 = fmaxf(o3, 0.f);
        }
        float4 ov = {o0, o1, o2, o3};
        *(float4*)(out + (size_t)r * Nout + cb) = ov;
    }
}

// ---------------- K5: token self-attention: T_dash = T + softmax(k q^T) T ----------------
__global__ __launch_bounds__(256) void k5_token_attn()
{
    int b = blockIdx.x;
    int tid = threadIdx.x;
    __shared__ float sc[16][16];
    __shared__ float wgt[16][16];

    {
        int i = tid >> 4, j = tid & 15;
        const float4* kr = (const float4*)(g_k + (size_t)(b * Lz + i) * C2z);
        const float4* qr = (const float4*)(g_q + (size_t)(b * Lz + j) * C2z);
        float s = 0.f;
        #pragma unroll 4
        for (int d = 0; d < C2z / 4; d++) {
            float4 a = kr[d], c = qr[d];
            s += a.x * c.x + a.y * c.y + a.z * c.z + a.w * c.w;
        }
        sc[i][j] = s;
    }
    __syncthreads();
    if (tid < 16) {
        float m = -INFINITY;
        #pragma unroll
        for (int j = 0; j < 16; j++) m = fmaxf(m, sc[tid][j]);
        float sum = 0.f;
        #pragma unroll
        for (int j = 0; j < 16; j++) { float e = expf(sc[tid][j] - m); wgt[tid][j] = e; sum += e; }
        float inv = 1.f / sum;
        #pragma unroll
        for (int j = 0; j < 16; j++) wgt[tid][j] *= inv;
    }
    __syncthreads();
    for (int c = tid; c < Cz; c += 256) {
        float t[16];
        #pragma unroll
        for (int j = 0; j < 16; j++) t[j] = g_T[(b * Lz + j) * Cz + c];
        #pragma unroll
        for (int i = 0; i < 16; i++) {
            float v = t[i];
            #pragma unroll
            for (int j = 0; j < 16; j++) v += wgt[i][j] * t[j];
            g_Td[(b * Lz + i) * Cz + c] = v;
        }
    }
}

// ---------------- K7: M[b][l][c] = sum_c' q_W[c][c'] * Tk[b][l][c'] ----------------
// Tk tile kept in smem in two 512-col halves (32KB).
__global__ __launch_bounds__(256) void k7_projM(const float* __restrict__ qW)
{
    __shared__ float Tks[16][CH];  // 32KB
    int b = blockIdx.y;
    int tid = threadIdx.x;
    int warp = tid >> 5, lane = tid & 31;
    int r0 = blockIdx.x * 32 + warp * 4;  // c rows of q_W

    float acc[4][16];
    #pragma unroll
    for (int i = 0; i < 4; i++)
        #pragma unroll
        for (int l = 0; l < 16; l++) acc[i][l] = 0.f;

    for (int ch = 0; ch < 2; ch++) {
        __syncthreads();
        for (int idx = tid; idx < 16 * CH; idx += 256) {
            int l = idx / CH, c = idx % CH;
            Tks[l][c] = g_Tk[b * Lz * Cz + l * Cz + ch * CH + c];
        }
        __syncthreads();

        const float4* q0 = (const float4*)(qW + (size_t)(r0 + 0) * Cz + ch * CH);
        const float4* q1 = (const float4*)(qW + (size_t)(r0 + 1) * Cz + ch * CH);
        const float4* q2 = (const float4*)(qW + (size_t)(r0 + 2) * Cz + ch * CH);
        const float4* q3 = (const float4*)(qW + (size_t)(r0 + 3) * Cz + ch * CH);
        const float4* T4 = (const float4*)Tks;

        #pragma unroll
        for (int jj = 0; jj < 4; jj++) {
            int c4 = jj * 32 + lane;
            float4 v0 = q0[c4], v1 = q1[c4], v2 = q2[c4], v3 = q3[c4];
            #pragma unroll
            for (int l = 0; l < 16; l++) {
                float4 t = T4[l * (CH / 4) + c4];
                acc[0][l] += v0.x * t.x + v0.y * t.y + v0.z * t.z + v0.w * t.w;
                acc[1][l] += v1.x * t.x + v1.y * t.y + v1.z * t.z + v1.w * t.w;
                acc[2][l] += v2.x * t.x + v2.y * t.y + v2.z * t.z + v2.w * t.w;
                acc[3][l] += v3.x * t.x + v3.y * t.y + v3.z * t.z + v3.w * t.w;
            }
        }
    }
    #pragma unroll
    for (int i = 0; i < 4; i++) {
        float myv = 0.f;
        #pragma unroll
        for (int l = 0; l < 16; l++) {
            float v = acc[i][l];
            v += __shfl_xor_sync(0xffffffffu, v, 16);
            v += __shfl_xor_sync(0xffffffffu, v, 8);
            v += __shfl_xor_sync(0xffffffffu, v, 4);
            v += __shfl_xor_sync(0xffffffffu, v, 2);
            v += __shfl_xor_sync(0xffffffffu, v, 1);
            if (lane == l) myv = v;
        }
        if (lane < 16) g_M[b * Lz * Cz + lane * Cz + (r0 + i)] = myv;
    }
}

// ---------------- s0[b][l] = q_b . Tk[b][l] ----------------
__global__ __launch_bounds__(512) void k_s0(const float* __restrict__ qb)
{
    int b = blockIdx.x;
    int warp = threadIdx.x >> 5, lane = threadIdx.x & 31;  // 16 warps, one per l
    float s = 0.f;
    for (int c = lane; c < Cz; c += 32) s += qb[c] * g_Tk[(b * Lz + warp) * Cz + c];
    s += __shfl_xor_sync(0xffffffffu, s, 16);
    s += __shfl_xor_sync(0xffffffffu, s, 8);
    s += __shfl_xor_sync(0xffffffffu, s, 4);
    s += __shfl_xor_sync(0xffffffffu, s, 2);
    s += __shfl_xor_sync(0xffffffffu, s, 1);
    if (lane == 0) g_s0[b * Lz + warp] = s;
}

// ---------------- K8: fused projector: X_out = X + softmax(X@M + s0) @ T_out ----------------
// 64 rows/block (512 thr, 16 warps x 4 rows). One 32KB smem buffer, 4 phases.
__global__ __launch_bounds__(512) void k8_final(
    const float* __restrict__ X, const float* __restrict__ Tout,
    float* __restrict__ Xout)
{
    __shared__ float buf[16][CH];  // 32KB, reused for M halves then T halves
    int b = blockIdx.y;
    int tid = threadIdx.x;
    int warp = tid >> 5, lane = tid & 31;
    int row0 = blockIdx.x * 64 + warp * 4;  // row within batch
    const float4* buf4 = (const float4*)buf;

    float s0v = (lane < 16) ? g_s0[b * Lz + lane] : 0.f;

    // ---- phase A: sim accumulation over two M halves ----
    float acc[4][16];
    #pragma unroll
    for (int i = 0; i < 4; i++)
        #pragma unroll
        for (int l = 0; l < 16; l++) acc[i][l] = 0.f;

    for (int ch = 0; ch < 2; ch++) {
        __syncthreads();
        for (int idx = tid; idx < 16 * CH; idx += 512) {
            int l = idx / CH, c = idx % CH;
            buf[l][c] = g_M[b * Lz * Cz + l * Cz + ch * CH + c];
        }
        __syncthreads();

        const float4* x0 = (const float4*)(X + (size_t)(b * Nz + row0 + 0) * Cz + ch * CH);
        const float4* x1 = (const float4*)(X + (size_t)(b * Nz + row0 + 1) * Cz + ch * CH);
        const float4* x2 = (const float4*)(X + (size_t)(b * Nz + row0 + 2) * Cz + ch * CH);
        const float4* x3 = (const float4*)(X + (size_t)(b * Nz + row0 + 3) * Cz + ch * CH);

        #pragma unroll
        for (int jj = 0; jj < 4; jj++) {
            int c4 = jj * 32 + lane;
            float4 xv0 = x0[c4], xv1 = x1[c4], xv2 = x2[c4], xv3 = x3[c4];
            #pragma unroll
            for (int l = 0; l < 16; l++) {
                float4 m = buf4[l * (CH / 4) + c4];
                acc[0][l] += xv0.x * m.x + xv0.y * m.y + xv0.z * m.z + xv0.w * m.w;
                acc[1][l] += xv1.x * m.x + xv1.y * m.y + xv1.z * m.z + xv1.w * m.w;
                acc[2][l] += xv2.x * m.x + xv2.y * m.y + xv2.z * m.z + xv2.w * m.w;
                acc[3][l] += xv3.x * m.x + xv3.y * m.y + xv3.z * m.z + xv3.w * m.w;
            }
        }
    }

    // ---- softmax weights per row ----
    float wv[4][16];
    #pragma unroll
    for (int i = 0; i < 4; i++) {
        float simv = 0.f;
        #pragma unroll
        for (int l = 0; l < 16; l++) {
            float v = acc[i][l];
            v += __shfl_xor_sync(0xffffffffu, v, 16);
            v += __shfl_xor_sync(0xffffffffu, v, 8);
            v += __shfl_xor_sync(0xffffffffu, v, 4);
            v += __shfl_xor_sync(0xffffffffu, v, 2);
            v += __shfl_xor_sync(0xffffffffu, v, 1);
            if (lane == l) simv = v;
        }
        simv += s0v;
        // mirror lanes 0..15 to 16..31 so width-16 reductions are valid
        simv = __shfl_sync(0xffffffffu, simv, lane & 15);
        float m = simv;
        m = fmaxf(m, __shfl_xor_sync(0xffffffffu, m, 8, 16));
        m = fmaxf(m, __shfl_xor_sync(0xffffffffu, m, 4, 16));
        m = fmaxf(m, __shfl_xor_sync(0xffffffffu, m, 2, 16));
        m = fmaxf(m, __shfl_xor_sync(0xffffffffu, m, 1, 16));
        float e = expf(simv - m);
        float ssum = e;
        ssum += __shfl_xor_sync(0xffffffffu, ssum, 8, 16);
        ssum += __shfl_xor_sync(0xffffffffu, ssum, 4, 16);
        ssum += __shfl_xor_sync(0xffffffffu, ssum, 2, 16);
        ssum += __shfl_xor_sync(0xffffffffu, ssum, 1, 16);
        float w = e / ssum;
        #pragma unroll
        for (int l = 0; l < 16; l++) wv[i][l] = __shfl_sync(0xffffffffu, w, l);
    }

    // ---- phase B: output over two T halves ----
    for (int ch = 0; ch < 2; ch++) {
        __syncthreads();
        for (int idx = tid; idx < 16 * CH; idx += 512) {
            int l = idx / CH, c = idx % CH;
            buf[l][c] = Tout[b * Lz * Cz + l * Cz + ch * CH + c];
        }
        __syncthreads();

        #pragma unroll
        for (int i = 0; i < 4; i++) {
            const float4* xr = (const float4*)(X + (size_t)(b * Nz + row0 + i) * Cz + ch * CH);
            float4* outr = (float4*)(Xout + (size_t)(b * Nz + row0 + i) * Cz + ch * CH);
            #pragma unroll
            for (int jj = 0; jj < 4; jj++) {
                int c4 = jj * 32 + lane;
                float4 o = xr[c4];
                #pragma unroll
                for (int l = 0; l < 16; l++) {
                    float4 t = buf4[l * (CH / 4) + c4];
                    float w = wv[i][l];
                    o.x += w * t.x; o.y += w * t.y;
                    o.z += w * t.z; o.w += w * t.w;
                }
                outr[c4] = o;
            }
        }
    }
}

// ---------------- host: PURE kernel launches (no other runtime APIs) ----------------
extern "C" void kernel_launch(void* const* d_in, const int* in_sizes, int n_in,
                              void* d_out, int out_size)
{
    const float* X       = (const float*)d_in[0];
    const float* tok_W   = (const float*)d_in[2];
    const float* tok_b   = (const float*)d_in[3];
    const float* key_W   = (const float*)d_in[4];
    const float* key_b   = (const float*)d_in[5];
    const float* query_W = (const float*)d_in[6];
    const float* query_b = (const float*)d_in[7];
    const float* f1_W    = (const float*)d_in[8];
    const float* f1_b    = (const float*)d_in[9];
    const float* f2_W    = (const float*)d_in[10];
    const float* f2_b    = (const float*)d_in[11];
    const float* q_W     = (const float*)d_in[12];
    const float* q_b     = (const float*)d_in[13];
    const float* k_W     = (const float*)d_in[14];
    const float* k_b     = (const float*)d_in[15];

    float* Xout = (float*)d_out;
    float* Tout = Xout + (size_t)Bz * Nz * Cz;

    // tokenizer
    k1_proj_exp<<<(Bz * Nz) / 32, 256>>>(X, tok_W, tok_b);
    k2_colsum<<<Bz, 512>>>();
    k3_aggregate<<<dim3(Cz / 128, Bz), 256>>>(X);

    // transformer block on tokens
    gemm_bias<0,0,0,0><<<dim3(C2z / 64, (Bz * Lz) / 64), 256>>>(nullptr, key_W,  key_b,  nullptr, Cz, C2z);
    gemm_bias<0,1,0,0><<<dim3(C2z / 64, (Bz * Lz) / 64), 256>>>(nullptr, query_W,query_b,nullptr, Cz, C2z);
    k5_token_attn<<<Bz, 256>>>();
    gemm_bias<1,2,0,1><<<dim3(Cz / 64, (Bz * Lz) / 64), 256>>>(nullptr, f1_W, f1_b, nullptr, Cz, Cz);
    gemm_bias<2,3,1,0><<<dim3(Cz / 64, (Bz * Lz) / 64), 256>>>(nullptr, f2_W, f2_b, Tout,    Cz, Cz);

    // projector (re-associated: sim = X @ (q_W @ Tk^T) + q_b.Tk)
    gemm_bias<3,4,0,0><<<dim3(Cz / 64, (Bz * Lz) / 64), 256>>>(Tout, k_W, k_b, nullptr, Cz, Cz);
    k7_projM<<<dim3(Cz / 32, Bz), 256>>>(q_W);
    k_s0<<<Bz, 512>>>(q_b);
    k8_final<<<dim3(Nz / 64, Bz), 512>>>(X, Tout, Xout);
}

// round 4
// speedup vs baseline: 1.0851x; 1.0851x over previous
#include <cuda_runtime.h>
#include <cuda_bf16.h>
#include <math.h>

// Problem dims
#define Bz 32
#define Nz 1024
#define Cz 1024
#define Lz 16
#define C2z 512
#define CH 512   // C-half tile

typedef unsigned long long ull;

// ---------------- scratch (static device memory, no allocs) ----------------
__device__ float g_E[Bz * Nz * Lz];      // exp(proj), unnormalized
__device__ float g_S[Bz * Lz];           // softmax column sums
__device__ float g_T[Bz * Lz * Cz];      // tokens
__device__ float g_k[Bz * Lz * C2z];
__device__ float g_q[Bz * Lz * C2z];
__device__ float g_Td[Bz * Lz * Cz];     // T_dash
__device__ float g_H[Bz * Lz * Cz];      // relu hidden
__device__ float g_Tk[Bz * Lz * Cz];     // T_out @ k_W + k_b
__device__ float g_M[Bz * Lz * Cz];      // M[b][l][c] = sum_c' q_W[c][c']*Tk[b][l][c']
__device__ float g_s0[Bz * Lz];          // q_b . Tk[b][l]

// ---- packed f32x2 helpers ----
__device__ __forceinline__ void fma2(ull& d, ull a, ull b) {
    asm("fma.rn.f32x2 %0, %1, %2, %0;" : "+l"(d) : "l"(a), "l"(b));
}
__device__ __forceinline__ ull pack2(float x) {
    ull r;
    asm("mov.b64 %0, {%1, %1};" : "=l"(r) : "f"(x));
    return r;
}
__device__ __forceinline__ float2 unpack2(ull u) {
    float2 f;
    asm("mov.b64 {%0, %1}, %2;" : "=f"(f.x), "=f"(f.y) : "l"(u));
    return f;
}

// ---------------- K1: E = exp(X @ tok_W + tok_b) ----------------
__global__ __launch_bounds__(256) void k1_proj_exp(
    const float* __restrict__ X, const float* __restrict__ tokW,
    const float* __restrict__ tokb)
{
    __shared__ float Ws[16][CH];  // 32KB
    int tid = threadIdx.x;
    int warp = tid >> 5, lane = tid & 31;
    int row0 = blockIdx.x * 32 + warp * 4;  // row in [0, B*N)

    float acc[4][16];
    #pragma unroll
    for (int i = 0; i < 4; i++)
        #pragma unroll
        for (int l = 0; l < 16; l++) acc[i][l] = 0.f;

    for (int ch = 0; ch < 2; ch++) {
        __syncthreads();
        for (int idx = tid; idx < CH * 16; idx += 256) {
            int c = idx >> 4, l = idx & 15;
            Ws[l][c] = tokW[(ch * CH + c) * Lz + l];
        }
        __syncthreads();

        const float4* x0 = (const float4*)(X + (size_t)(row0 + 0) * Cz + ch * CH);
        const float4* x1 = (const float4*)(X + (size_t)(row0 + 1) * Cz + ch * CH);
        const float4* x2 = (const float4*)(X + (size_t)(row0 + 2) * Cz + ch * CH);
        const float4* x3 = (const float4*)(X + (size_t)(row0 + 3) * Cz + ch * CH);
        const float4* Ws4 = (const float4*)Ws;

        #pragma unroll
        for (int jj = 0; jj < 4; jj++) {
            int c4 = jj * 32 + lane;
            float4 xv0 = x0[c4], xv1 = x1[c4], xv2 = x2[c4], xv3 = x3[c4];
            #pragma unroll
            for (int l = 0; l < 16; l++) {
                float4 w = Ws4[l * (CH / 4) + c4];
                acc[0][l] += xv0.x * w.x + xv0.y * w.y + xv0.z * w.z + xv0.w * w.w;
                acc[1][l] += xv1.x * w.x + xv1.y * w.y + xv1.z * w.z + xv1.w * w.w;
                acc[2][l] += xv2.x * w.x + xv2.y * w.y + xv2.z * w.z + xv2.w * w.w;
                acc[3][l] += xv3.x * w.x + xv3.y * w.y + xv3.z * w.z + xv3.w * w.w;
            }
        }
    }
    float bv = (lane < 16) ? tokb[lane] : 0.f;
    #pragma unroll
    for (int i = 0; i < 4; i++) {
        float myv = 0.f;
        #pragma unroll
        for (int l = 0; l < 16; l++) {
            float v = acc[i][l];
            v += __shfl_xor_sync(0xffffffffu, v, 16);
            v += __shfl_xor_sync(0xffffffffu, v, 8);
            v += __shfl_xor_sync(0xffffffffu, v, 4);
            v += __shfl_xor_sync(0xffffffffu, v, 2);
            v += __shfl_xor_sync(0xffffffffu, v, 1);
            if (lane == l) myv = v;
        }
        if (lane < 16) g_E[(row0 + i) * Lz + lane] = expf(myv + bv);
    }
}

// ---------------- K2: S[b][l] = sum_n E[b][n][l] ----------------
__global__ __launch_bounds__(512) void k2_colsum()
{
    int b = blockIdx.x;
    int tid = threadIdx.x;
    int l = tid & 15, ng = tid >> 4;  // 32 groups
    float s = 0.f;
    for (int n = ng; n < Nz; n += 32) s += g_E[(b * Nz + n) * Lz + l];
    __shared__ float red[32][16];
    red[ng][l] = s;
    __syncthreads();
    if (tid < 16) {
        float t = 0.f;
        #pragma unroll
        for (int g = 0; g < 32; g++) t += red[g][tid];
        g_S[b * Lz + tid] = t;
    }
}

// ---------------- K3: T[b][l][c] = (1/S) sum_n E[b][n][l] * X[b][n][c] ----------------
__global__ __launch_bounds__(256) void k3_aggregate(const float* __restrict__ X)
{
    int b = blockIdx.y;
    int c0 = blockIdx.x * 128;
    int tid = threadIdx.x;
    int tx = tid & 127, ty = tid >> 7;  // ty in {0,1}

    __shared__ float Es[64][16];
    __shared__ float red[16][128];

    float acc[16];
    #pragma unroll
    for (int l = 0; l < 16; l++) acc[l] = 0.f;

    for (int n0 = 0; n0 < Nz; n0 += 64) {
        __syncthreads();
        for (int idx = tid; idx < 64 * 16; idx += 256)
            Es[idx >> 4][idx & 15] = g_E[(b * Nz + n0 + (idx >> 4)) * Lz + (idx & 15)];
        __syncthreads();
        #pragma unroll 4
        for (int jj = 0; jj < 32; jj++) {
            int nl = jj * 2 + ty;
            float x = X[(size_t)(b * Nz + n0 + nl) * Cz + c0 + tx];
            #pragma unroll
            for (int l = 0; l < 16; l++) acc[l] += Es[nl][l] * x;
        }
    }
    __syncthreads();
    if (ty == 1) {
        #pragma unroll
        for (int l = 0; l < 16; l++) red[l][tx] = acc[l];
    }
    __syncthreads();
    if (ty == 0) {
        #pragma unroll
        for (int l = 0; l < 16; l++) {
            float v = acc[l] + red[l][tx];
            g_T[(b * Lz + l) * Cz + c0 + tx] = v / g_S[b * Lz + l];
        }
    }
}

// ---------------- GEMM v2: 128 thr, BM=64 BN=64 BK=32, double-buffered, f32x2 ----------------
// ASEL: 0=g_T 1=g_Td 2=g_H 3=Aext   OSEL: 5=(z? g_q : g_k) 2=g_H 4=g_Tk 3=Oext
// RSEL: 0=none 1=g_Td   K fixed = Cz.
template<int ASEL, int OSEL, int RSEL, int RELU, int NOUT>
__global__ __launch_bounds__(128) void gemm_v2(
    const float* __restrict__ Aext,
    const float* __restrict__ Wa, const float* __restrict__ ba,
    const float* __restrict__ Wb, const float* __restrict__ bb,
    float* __restrict__ Oext)
{
    const float* A = (ASEL == 0) ? g_T : (ASEL == 1) ? g_Td : (ASEL == 2) ? g_H : Aext;
    int z = blockIdx.z;
    const float* W    = z ? Wb : Wa;
    const float* bias = z ? bb : ba;
    float* out = (OSEL == 5) ? (z ? g_q : g_k)
               : (OSEL == 2) ? g_H : (OSEL == 4) ? g_Tk : Oext;

    __shared__ float As[2][32][68];   // [k][m], padded (stride 68) for store conflicts
    __shared__ float Ws[2][32][64];   // [k][n]

    int tid = threadIdx.x;
    int c0 = blockIdx.x * 64;
    int r0 = blockIdx.y * 64;
    int tm = tid >> 3;    // 0..15 -> rows tm*4
    int tn = tid & 7;     // 0..7  -> cols tn*8

    // stage 0 load
    #pragma unroll
    for (int j = 0; j < 4; j++) {
        int idx = tid + j * 128;
        int row = idx >> 3, kq = (idx & 7) << 2;
        float4 a = *(const float4*)(A + (size_t)(r0 + row) * Cz + kq);
        As[0][kq + 0][row] = a.x; As[0][kq + 1][row] = a.y;
        As[0][kq + 2][row] = a.z; As[0][kq + 3][row] = a.w;
        int wrow = idx >> 4, wc4 = (idx & 15) << 2;
        *(float4*)&Ws[0][wrow][wc4] = *(const float4*)(W + (size_t)wrow * NOUT + c0 + wc4);
    }
    __syncthreads();

    ull acc[4][4];
    #pragma unroll
    for (int i = 0; i < 4; i++)
        #pragma unroll
        for (int j = 0; j < 4; j++) acc[i][j] = 0ULL;

    int s = 0;
    for (int k0 = 0; k0 < Cz; k0 += 32) {
        float4 ar[4], wr[4];
        bool more = (k0 + 32) < Cz;
        if (more) {
            #pragma unroll
            for (int j = 0; j < 4; j++) {
                int idx = tid + j * 128;
                int row = idx >> 3, kq = (idx & 7) << 2;
                ar[j] = *(const float4*)(A + (size_t)(r0 + row) * Cz + k0 + 32 + kq);
                int wrow = idx >> 4, wc4 = (idx & 15) << 2;
                wr[j] = *(const float4*)(W + (size_t)(k0 + 32 + wrow) * NOUT + c0 + wc4);
            }
        }
        #pragma unroll
        for (int kk = 0; kk < 32; kk++) {
            float4 av = *(const float4*)&As[s][kk][tm << 2];
            ulonglong2 w01 = *(const ulonglong2*)&Ws[s][kk][tn << 3];
            ulonglong2 w23 = *(const ulonglong2*)&Ws[s][kk][(tn << 3) + 4];
            ull a0 = pack2(av.x), a1 = pack2(av.y), a2 = pack2(av.z), a3 = pack2(av.w);
            fma2(acc[0][0], a0, w01.x); fma2(acc[0][1], a0, w01.y);
            fma2(acc[0][2], a0, w23.x); fma2(acc[0][3], a0, w23.y);
            fma2(acc[1][0], a1, w01.x); fma2(acc[1][1], a1, w01.y);
            fma2(acc[1][2], a1, w23.x); fma2(acc[1][3], a1, w23.y);
            fma2(acc[2][0], a2, w01.x); fma2(acc[2][1], a2, w01.y);
            fma2(acc[2][2], a2, w23.x); fma2(acc[2][3], a2, w23.y);
            fma2(acc[3][0], a3, w01.x); fma2(acc[3][1], a3, w01.y);
            fma2(acc[3][2], a3, w23.x); fma2(acc[3][3], a3, w23.y);
        }
        if (more) {
            #pragma unroll
            for (int j = 0; j < 4; j++) {
                int idx = tid + j * 128;
                int row = idx >> 3, kq = (idx & 7) << 2;
                As[s ^ 1][kq + 0][row] = ar[j].x; As[s ^ 1][kq + 1][row] = ar[j].y;
                As[s ^ 1][kq + 2][row] = ar[j].z; As[s ^ 1][kq + 3][row] = ar[j].w;
                int wrow = idx >> 4, wc4 = (idx & 15) << 2;
                *(float4*)&Ws[s ^ 1][wrow][wc4] = wr[j];
            }
        }
        __syncthreads();
        s ^= 1;
    }

    float4 b0v = *(const float4*)(bias + c0 + (tn << 3));
    float4 b1v = *(const float4*)(bias + c0 + (tn << 3) + 4);
    #pragma unroll
    for (int i = 0; i < 4; i++) {
        int r = r0 + (tm << 2) + i;
        float2 p0 = unpack2(acc[i][0]), p1 = unpack2(acc[i][1]);
        float2 p2 = unpack2(acc[i][2]), p3 = unpack2(acc[i][3]);
        float o0 = p0.x + b0v.x, o1 = p0.y + b0v.y, o2 = p1.x + b0v.z, o3 = p1.y + b0v.w;
        float o4 = p2.x + b1v.x, o5 = p2.y + b1v.y, o6 = p3.x + b1v.z, o7 = p3.y + b1v.w;
        if (RSEL == 1) {
            float4 rv0 = *(const float4*)(g_Td + (size_t)r * NOUT + c0 + (tn << 3));
            float4 rv1 = *(const float4*)(g_Td + (size_t)r * NOUT + c0 + (tn << 3) + 4);
            o0 += rv0.x; o1 += rv0.y; o2 += rv0.z; o3 += rv0.w;
            o4 += rv1.x; o5 += rv1.y; o6 += rv1.z; o7 += rv1.w;
        }
        if (RELU) {
            o0 = fmaxf(o0, 0.f); o1 = fmaxf(o1, 0.f); o2 = fmaxf(o2, 0.f); o3 = fmaxf(o3, 0.f);
            o4 = fmaxf(o4, 0.f); o5 = fmaxf(o5, 0.f); o6 = fmaxf(o6, 0.f); o7 = fmaxf(o7, 0.f);
        }
        float4 ov0 = {o0, o1, o2, o3};
        float4 ov1 = {o4, o5, o6, o7};
        *(float4*)(out + (size_t)r * NOUT + c0 + (tn << 3)) = ov0;
        *(float4*)(out + (size_t)r * NOUT + c0 + (tn << 3) + 4) = ov1;
    }
}

// ---------------- K5: token self-attention: T_dash = T + softmax(k q^T) T ----------------
__global__ __launch_bounds__(256) void k5_token_attn()
{
    int b = blockIdx.x;
    int tid = threadIdx.x;
    __shared__ float sc[16][16];
    __shared__ float wgt[16][16];

    {
        int i = tid >> 4, j = tid & 15;
        const float4* kr = (const float4*)(g_k + (size_t)(b * Lz + i) * C2z);
        const float4* qr = (const float4*)(g_q + (size_t)(b * Lz + j) * C2z);
        float s = 0.f;
        #pragma unroll 4
        for (int d = 0; d < C2z / 4; d++) {
            float4 a = kr[d], c = qr[d];
            s += a.x * c.x + a.y * c.y + a.z * c.z + a.w * c.w;
        }
        sc[i][j] = s;
    }
    __syncthreads();
    if (tid < 16) {
        float m = -INFINITY;
        #pragma unroll
        for (int j = 0; j < 16; j++) m = fmaxf(m, sc[tid][j]);
        float sum = 0.f;
        #pragma unroll
        for (int j = 0; j < 16; j++) { float e = expf(sc[tid][j] - m); wgt[tid][j] = e; sum += e; }
        float inv = 1.f / sum;
        #pragma unroll
        for (int j = 0; j < 16; j++) wgt[tid][j] *= inv;
    }
    __syncthreads();
    for (int c = tid; c < Cz; c += 256) {
        float t[16];
        #pragma unroll
        for (int j = 0; j < 16; j++) t[j] = g_T[(b * Lz + j) * Cz + c];
        #pragma unroll
        for (int i = 0; i < 16; i++) {
            float v = t[i];
            #pragma unroll
            for (int j = 0; j < 16; j++) v += wgt[i][j] * t[j];
            g_Td[(b * Lz + i) * Cz + c] = v;
        }
    }
}

// ---------------- K7: M[b][l][c] = sum_c' q_W[c][c'] * Tk[b][l][c'] ----------------
__global__ __launch_bounds__(256) void k7_projM(const float* __restrict__ qW)
{
    __shared__ float Tks[16][CH];  // 32KB
    int b = blockIdx.y;
    int tid = threadIdx.x;
    int warp = tid >> 5, lane = tid & 31;
    int r0 = blockIdx.x * 32 + warp * 4;  // c rows of q_W

    float acc[4][16];
    #pragma unroll
    for (int i = 0; i < 4; i++)
        #pragma unroll
        for (int l = 0; l < 16; l++) acc[i][l] = 0.f;

    for (int ch = 0; ch < 2; ch++) {
        __syncthreads();
        for (int idx = tid; idx < 16 * CH; idx += 256) {
            int l = idx / CH, c = idx % CH;
            Tks[l][c] = g_Tk[b * Lz * Cz + l * Cz + ch * CH + c];
        }
        __syncthreads();

        const float4* q0 = (const float4*)(qW + (size_t)(r0 + 0) * Cz + ch * CH);
        const float4* q1 = (const float4*)(qW + (size_t)(r0 + 1) * Cz + ch * CH);
        const float4* q2 = (const float4*)(qW + (size_t)(r0 + 2) * Cz + ch * CH);
        const float4* q3 = (const float4*)(qW + (size_t)(r0 + 3) * Cz + ch * CH);
        const float4* T4 = (const float4*)Tks;

        #pragma unroll
        for (int jj = 0; jj < 4; jj++) {
            int c4 = jj * 32 + lane;
            float4 v0 = q0[c4], v1 = q1[c4], v2 = q2[c4], v3 = q3[c4];
            #pragma unroll
            for (int l = 0; l < 16; l++) {
                float4 t = T4[l * (CH / 4) + c4];
                acc[0][l] += v0.x * t.x + v0.y * t.y + v0.z * t.z + v0.w * t.w;
                acc[1][l] += v1.x * t.x + v1.y * t.y + v1.z * t.z + v1.w * t.w;
                acc[2][l] += v2.x * t.x + v2.y * t.y + v2.z * t.z + v2.w * t.w;
                acc[3][l] += v3.x * t.x + v3.y * t.y + v3.z * t.z + v3.w * t.w;
            }
        }
    }
    #pragma unroll
    for (int i = 0; i < 4; i++) {
        float myv = 0.f;
        #pragma unroll
        for (int l = 0; l < 16; l++) {
            float v = acc[i][l];
            v += __shfl_xor_sync(0xffffffffu, v, 16);
            v += __shfl_xor_sync(0xffffffffu, v, 8);
            v += __shfl_xor_sync(0xffffffffu, v, 4);
            v += __shfl_xor_sync(0xffffffffu, v, 2);
            v += __shfl_xor_sync(0xffffffffu, v, 1);
            if (lane == l) myv = v;
        }
        if (lane < 16) g_M[b * Lz * Cz + lane * Cz + (r0 + i)] = myv;
    }
}

// ---------------- s0[b][l] = q_b . Tk[b][l] ----------------
__global__ __launch_bounds__(512) void k_s0(const float* __restrict__ qb)
{
    int b = blockIdx.x;
    int warp = threadIdx.x >> 5, lane = threadIdx.x & 31;  // 16 warps, one per l
    float s = 0.f;
    for (int c = lane; c < Cz; c += 32) s += qb[c] * g_Tk[(b * Lz + warp) * Cz + c];
    s += __shfl_xor_sync(0xffffffffu, s, 16);
    s += __shfl_xor_sync(0xffffffffu, s, 8);
    s += __shfl_xor_sync(0xffffffffu, s, 4);
    s += __shfl_xor_sync(0xffffffffu, s, 2);
    s += __shfl_xor_sync(0xffffffffu, s, 1);
    if (lane == 0) g_s0[b * Lz + warp] = s;
}

// ---------------- K8: fused projector: X_out = X + softmax(X@M + s0) @ T_out ----------------
__global__ __launch_bounds__(512) void k8_final(
    const float* __restrict__ X, const float* __restrict__ Tout,
    float* __restrict__ Xout)
{
    __shared__ float buf[16][CH];  // 32KB, reused for M halves then T halves
    int b = blockIdx.y;
    int tid = threadIdx.x;
    int warp = tid >> 5, lane = tid & 31;
    int row0 = blockIdx.x * 64 + warp * 4;  // row within batch
    const float4* buf4 = (const float4*)buf;

    float s0v = (lane < 16) ? g_s0[b * Lz + lane] : 0.f;

    // ---- phase A: sim accumulation over two M halves ----
    float acc[4][16];
    #pragma unroll
    for (int i = 0; i < 4; i++)
        #pragma unroll
        for (int l = 0; l < 16; l++) acc[i][l] = 0.f;

    for (int ch = 0; ch < 2; ch++) {
        __syncthreads();
        for (int idx = tid; idx < 16 * CH; idx += 512) {
            int l = idx / CH, c = idx % CH;
            buf[l][c] = g_M[b * Lz * Cz + l * Cz + ch * CH + c];
        }
        __syncthreads();

        const float4* x0 = (const float4*)(X + (size_t)(b * Nz + row0 + 0) * Cz + ch * CH);
        const float4* x1 = (const float4*)(X + (size_t)(b * Nz + row0 + 1) * Cz + ch * CH);
        const float4* x2 = (const float4*)(X + (size_t)(b * Nz + row0 + 2) * Cz + ch * CH);
        const float4* x3 = (const float4*)(X + (size_t)(b * Nz + row0 + 3) * Cz + ch * CH);

        #pragma unroll
        for (int jj = 0; jj < 4; jj++) {
            int c4 = jj * 32 + lane;
            float4 xv0 = x0[c4], xv1 = x1[c4], xv2 = x2[c4], xv3 = x3[c4];
            #pragma unroll
            for (int l = 0; l < 16; l++) {
                float4 m = buf4[l * (CH / 4) + c4];
                acc[0][l] += xv0.x * m.x + xv0.y * m.y + xv0.z * m.z + xv0.w * m.w;
                acc[1][l] += xv1.x * m.x + xv1.y * m.y + xv1.z * m.z + xv1.w * m.w;
                acc[2][l] += xv2.x * m.x + xv2.y * m.y + xv2.z * m.z + xv2.w * m.w;
                acc[3][l] += xv3.x * m.x + xv3.y * m.y + xv3.z * m.z + xv3.w * m.w;
            }
        }
    }

    // ---- softmax weights per row ----
    float wv[4][16];
    #pragma unroll
    for (int i = 0; i < 4; i++) {
        float simv = 0.f;
        #pragma unroll
        for (int l = 0; l < 16; l++) {
            float v = acc[i][l];
            v += __shfl_xor_sync(0xffffffffu, v, 16);
            v += __shfl_xor_sync(0xffffffffu, v, 8);
            v += __shfl_xor_sync(0xffffffffu, v, 4);
            v += __shfl_xor_sync(0xffffffffu, v, 2);
            v += __shfl_xor_sync(0xffffffffu, v, 1);
            if (lane == l) simv = v;
        }
        simv += s0v;
        simv = __shfl_sync(0xffffffffu, simv, lane & 15);
        float m = simv;
        m = fmaxf(m, __shfl_xor_sync(0xffffffffu, m, 8, 16));
        m = fmaxf(m, __shfl_xor_sync(0xffffffffu, m, 4, 16));
        m = fmaxf(m, __shfl_xor_sync(0xffffffffu, m, 2, 16));
        m = fmaxf(m, __shfl_xor_sync(0xffffffffu, m, 1, 16));
        float e = expf(simv - m);
        float ssum = e;
        ssum += __shfl_xor_sync(0xffffffffu, ssum, 8, 16);
        ssum += __shfl_xor_sync(0xffffffffu, ssum, 4, 16);
        ssum += __shfl_xor_sync(0xffffffffu, ssum, 2, 16);
        ssum += __shfl_xor_sync(0xffffffffu, ssum, 1, 16);
        float w = e / ssum;
        #pragma unroll
        for (int l = 0; l < 16; l++) wv[i][l] = __shfl_sync(0xffffffffu, w, l);
    }

    // ---- phase B: output over two T halves ----
    for (int ch = 0; ch < 2; ch++) {
        __syncthreads();
        for (int idx = tid; idx < 16 * CH; idx += 512) {
            int l = idx / CH, c = idx % CH;
            buf[l][c] = Tout[b * Lz * Cz + l * Cz + ch * CH + c];
        }
        __syncthreads();

        #pragma unroll
        for (int i = 0; i < 4; i++) {
            const float4* xr = (const float4*)(X + (size_t)(b * Nz + row0 + i) * Cz + ch * CH);
            float4* outr = (float4*)(Xout + (size_t)(b * Nz + row0 + i) * Cz + ch * CH);
            #pragma unroll
            for (int jj = 0; jj < 4; jj++) {
                int c4 = jj * 32 + lane;
                float4 o = xr[c4];
                #pragma unroll
                for (int l = 0; l < 16; l++) {
                    float4 t = buf4[l * (CH / 4) + c4];
                    float w = wv[i][l];
                    o.x += w * t.x; o.y += w * t.y;
                    o.z += w * t.z; o.w += w * t.w;
                }
                outr[c4] = o;
            }
        }
    }
}

// ---------------- host: PURE kernel launches ----------------
extern "C" void kernel_launch(void* const* d_in, const int* in_sizes, int n_in,
                              void* d_out, int out_size)
{
    const float* X       = (const float*)d_in[0];
    const float* tok_W   = (const float*)d_in[2];
    const float* tok_b   = (const float*)d_in[3];
    const float* key_W   = (const float*)d_in[4];
    const float* key_b   = (const float*)d_in[5];
    const float* query_W = (const float*)d_in[6];
    const float* query_b = (const float*)d_in[7];
    const float* f1_W    = (const float*)d_in[8];
    const float* f1_b    = (const float*)d_in[9];
    const float* f2_W    = (const float*)d_in[10];
    const float* f2_b    = (const float*)d_in[11];
    const float* q_W     = (const float*)d_in[12];
    const float* q_b     = (const float*)d_in[13];
    const float* k_W     = (const float*)d_in[14];
    const float* k_b     = (const float*)d_in[15];

    float* Xout = (float*)d_out;
    float* Tout = Xout + (size_t)Bz * Nz * Cz;

    // tokenizer
    k1_proj_exp<<<(Bz * Nz) / 32, 256>>>(X, tok_W, tok_b);
    k2_colsum<<<Bz, 512>>>();
    k3_aggregate<<<dim3(Cz / 128, Bz), 256>>>(X);

    // transformer block on tokens (key+query fused via blockIdx.z)
    gemm_v2<0,5,0,0,512><<<dim3(8, 8, 2), 128>>>(nullptr, key_W, key_b, query_W, query_b, nullptr);
    k5_token_attn<<<Bz, 256>>>();
    gemm_v2<1,2,0,1,1024><<<dim3(16, 8, 1), 128>>>(nullptr, f1_W, f1_b, f1_W, f1_b, nullptr);
    gemm_v2<2,3,1,0,1024><<<dim3(16, 8, 1), 128>>>(nullptr, f2_W, f2_b, f2_W, f2_b, Tout);

    // projector (re-associated: sim = X @ (q_W @ Tk^T) + q_b.Tk)
    gemm_v2<3,4,0,0,1024><<<dim3(16, 8, 1), 128>>>(Tout, k_W, k_b, k_W, k_b, nullptr);
    k7_projM<<<dim3(Cz / 32, Bz), 256>>>(q_W);
    k_s0<<<Bz, 512>>>(q_b);
    k8_final<<<dim3(Nz / 64, Bz), 512>>>(X, Tout, Xout);
}